// round 7
// baseline (speedup 1.0000x reference)
#include <cuda_runtime.h>
#include <cuda_fp16.h>

#define NODELEN 10
#define DEG 32
#define MAXN 200000
#define PADH 16   // halves per row: 32B = one sector, sector-aligned

// Allocation-free scratch: fp16 gather tables, one sector per row.
__device__ __half g_featH[(size_t)MAXN * PADH];
__device__ __half g_h1H[(size_t)MAXN * PADH];

// ---------------------------------------------------------------------------
// Pack: features [N,10] fp32 -> g_featH [N,16] fp16 (zero padded).
// ---------------------------------------------------------------------------
__global__ __launch_bounds__(256) void pack_features_kernel(
    const float* __restrict__ features, int N)
{
    int idx = blockIdx.x * blockDim.x + threadIdx.x;
    if (idx >= N * PADH) return;
    int n = idx >> 4;
    int k = idx & 15;
    float v = (k < NODELEN) ? features[(size_t)n * NODELEN + k] : 0.f;
    g_featH[idx] = __float2half_rn(v);
}

// ---------------------------------------------------------------------------
// Hop kernels: one warp per TWO nodes (16 independent gather LDGs in flight).
// Lane l: r = l>>3 (row-in-group 0..3), j = l&7 (dim pair). Each gathered row
// is 16 halves = 32B = ONE sector. Butterfly-reduce over r (xor 8,16).
// After reduction every lane holds full 32-row sums for its j, both nodes.
// ---------------------------------------------------------------------------
__global__ __launch_bounds__(256) void hop1_kernel(
    const int* __restrict__ adj, int N)
{
    int w    = (blockIdx.x * blockDim.x + threadIdx.x) >> 5;
    int lane = threadIdx.x & 31;
    int n0 = 2 * w, n1 = 2 * w + 1;
    if (n0 >= N) return;
    bool has1 = (n1 < N);

    int nb0 = adj[(size_t)n0 * DEG + lane];
    int nb1 = has1 ? adj[(size_t)n1 * DEG + lane] : nb0;

    int r = lane >> 3, j = lane & 7;
    float2 a0 = make_float2(0.f, 0.f), a1 = make_float2(0.f, 0.f);
#pragma unroll
    for (int i = 0; i < 8; i++) {
        int m0 = __shfl_sync(0xffffffffu, nb0, 4 * i + r);
        int m1 = __shfl_sync(0xffffffffu, nb1, 4 * i + r);
        float2 v0 = __half22float2(*reinterpret_cast<const __half2*>(
            g_featH + (size_t)m0 * PADH + 2 * j));
        float2 v1 = __half22float2(*reinterpret_cast<const __half2*>(
            g_featH + (size_t)m1 * PADH + 2 * j));
        a0.x += v0.x; a0.y += v0.y;
        a1.x += v1.x; a1.y += v1.y;
    }
#pragma unroll
    for (int off = 8; off < 32; off <<= 1) {
        a0.x += __shfl_xor_sync(0xffffffffu, a0.x, off);
        a0.y += __shfl_xor_sync(0xffffffffu, a0.y, off);
        a1.x += __shfl_xor_sync(0xffffffffu, a1.x, off);
        a1.y += __shfl_xor_sync(0xffffffffu, a1.y, off);
    }

    if (lane < 16) {
        int   node = (lane >> 3) ? n1 : n0;
        float2 s   = (lane >> 3) ? a1 : a0;
        if (node < N) {
            float vx = s.x * (1.f / 32.f);
            float vy = s.y * (1.f / 32.f);
            if (j == 0) vx = 0.f;            // h1[:,0] = 0
            *reinterpret_cast<__half2*>(g_h1H + (size_t)node * PADH + 2 * j) =
                __floats2half2_rn(vx, vy);
        }
    }
}

__global__ __launch_bounds__(256) void hop2_emb_kernel(
    const float* __restrict__ features, const int* __restrict__ adj,
    float* __restrict__ emb, int N)
{
    int w    = (blockIdx.x * blockDim.x + threadIdx.x) >> 5;
    int lane = threadIdx.x & 31;
    int n0 = 2 * w, n1 = 2 * w + 1;
    if (n0 >= N) return;
    bool has1 = (n1 < N);

    int nb0 = adj[(size_t)n0 * DEG + lane];
    int nb1 = has1 ? adj[(size_t)n1 * DEG + lane] : nb0;

    int r = lane >> 3, j = lane & 7;
    float2 a0 = make_float2(0.f, 0.f), a1 = make_float2(0.f, 0.f);
#pragma unroll
    for (int i = 0; i < 8; i++) {
        int m0 = __shfl_sync(0xffffffffu, nb0, 4 * i + r);
        int m1 = __shfl_sync(0xffffffffu, nb1, 4 * i + r);
        float2 v0 = __half22float2(*reinterpret_cast<const __half2*>(
            g_h1H + (size_t)m0 * PADH + 2 * j));
        float2 v1 = __half22float2(*reinterpret_cast<const __half2*>(
            g_h1H + (size_t)m1 * PADH + 2 * j));
        a0.x += v0.x; a0.y += v0.y;
        a1.x += v1.x; a1.y += v1.y;
    }
#pragma unroll
    for (int off = 8; off < 32; off <<= 1) {
        a0.x += __shfl_xor_sync(0xffffffffu, a0.x, off);
        a0.y += __shfl_xor_sync(0xffffffffu, a0.y, off);
        a1.x += __shfl_xor_sync(0xffffffffu, a1.x, off);
        a1.y += __shfl_xor_sync(0xffffffffu, a1.y, off);
    }

    // agg part: cols 10..19 (pairs j=0..4), col 10 zeroed
    if (lane < 16 && j < 5) {
        int    node = (lane >> 3) ? n1 : n0;
        float2 s    = (lane >> 3) ? a1 : a0;
        if (node < N) {
            float2 v;
            v.x = s.x * (1.f / 32.f);
            v.y = s.y * (1.f / 32.f);
            if (j == 0) v.x = 0.f;           // emb[:,NODELEN] = 0
            *reinterpret_cast<float2*>(emb + (size_t)node * 20 + 10 + 2 * j) = v;
        }
    }
    // self features: cols 0..9, col 0 zeroed (exact fp32 from input)
    if (lane >= 12) {
        int d, node;
        if (lane < 22) { d = lane - 12; node = n0; }
        else           { d = lane - 22; node = n1; }
        if (node < N) {
            float f = (d == 0) ? 0.f : features[(size_t)node * NODELEN + d];
            emb[(size_t)node * 20 + d] = f;
        }
    }
}

// ---------------------------------------------------------------------------
// MLP autoencoder: each thread processes TWO nodes packed into f32x2 lanes,
// using sm_103a packed fma.rn.f32x2 (FFMA2). Weights stored DUPLICATED in
// shared memory so an 8-byte LDS yields (w,w) with no pack instruction.
// ---------------------------------------------------------------------------
#define MLP_BLK 128
#define MLP_TILE (2 * MLP_BLK)   // 256 nodes per block
#define EMB_PAD 21               // odd stride -> conflict-free LDS

typedef unsigned long long u64;

__device__ __forceinline__ u64 pk2(float lo, float hi) {
    u64 r; asm("mov.b64 %0,{%1,%2};" : "=l"(r) : "f"(lo), "f"(hi)); return r;
}
__device__ __forceinline__ void up2(u64 v, float& lo, float& hi) {
    asm("mov.b64 {%0,%1},%2;" : "=f"(lo), "=f"(hi) : "l"(v));
}
__device__ __forceinline__ u64 fma2(u64 a, u64 b, u64 c) {
    u64 d; asm("fma.rn.f32x2 %0,%1,%2,%3;" : "=l"(d) : "l"(a), "l"(b), "l"(c));
    return d;
}
__device__ __forceinline__ u64 relu2(u64 v) {
    float lo, hi; up2(v, lo, hi);
    return pk2(fmaxf(lo, 0.f), fmaxf(hi, 0.f));
}

__global__ __launch_bounds__(MLP_BLK) void mlp_kernel(
    const float* __restrict__ emb,
    const float* __restrict__ We1, const float* __restrict__ be1,
    const float* __restrict__ We2, const float* __restrict__ be2,
    const float* __restrict__ We3, const float* __restrict__ be3,
    const float* __restrict__ Wd1, const float* __restrict__ bd1,
    const float* __restrict__ Wd2, const float* __restrict__ bd2,
    const float* __restrict__ Wd3, const float* __restrict__ bd3,
    float* __restrict__ enc_out, float* __restrict__ dec_out, int N)
{
    __shared__ __align__(16) float sw[2150];          // duplicated weights
    __shared__ float se[MLP_TILE * EMB_PAD];          // emb / decoded tile

    const int tid = threadIdx.x;
    {
        const float* srcs[12] = {We1, We2, We3, Wd1, Wd2, Wd3,
                                 be1, be2, be3, bd1, bd2, bd3};
        const int off[12] = {0, 600, 900, 1000, 1100, 1400,
                             2000, 2030, 2050, 2060, 2080, 2110};
        const int sz[12]  = {300, 150, 50, 50, 150, 300,
                             15, 10, 5, 10, 15, 20};
#pragma unroll
        for (int a = 0; a < 12; a++)
            for (int k = tid; k < sz[a]; k += MLP_BLK) {
                float v = srcs[a][k];
                sw[off[a] + 2 * k]     = v;
                sw[off[a] + 2 * k + 1] = v;
            }
    }

    // stage emb tile: coalesced float4 loads, OOB rows zeroed
    const int  base    = blockIdx.x * MLP_TILE;
    const long f4base  = (long)base * 5;
    const long f4total = (long)N * 5;
#pragma unroll
    for (int i = 0; i < 10; i++) {
        int  lf4 = tid + i * MLP_BLK;                 // 0..1279
        long f4  = f4base + lf4;
        float4 t = (f4 < f4total) ? reinterpret_cast<const float4*>(emb)[f4]
                                  : make_float4(0.f, 0.f, 0.f, 0.f);
        int rr = lf4 / 5, q = lf4 % 5;
        float* d = se + rr * EMB_PAD + q * 4;
        d[0] = t.x; d[1] = t.y; d[2] = t.z; d[3] = t.w;
    }
    __syncthreads();

    const int n0 = base + tid;
    const int n1 = base + MLP_BLK + tid;

    // duplicated-weight views (u64 index = float offset / 2)
    const u64* wWe1 = (const u64*)(sw);          // [15][20]
    const u64* wWe2 = (const u64*)(sw) + 300;    // [10][15]
    const u64* wWe3 = (const u64*)(sw) + 450;    // [5][10]
    const u64* wWd1 = (const u64*)(sw) + 500;    // [10][5]
    const u64* wWd2 = (const u64*)(sw) + 550;    // [15][10]
    const u64* wWd3 = (const u64*)(sw) + 700;    // [20][15]
    const u64* vbe1 = (const u64*)(sw) + 1000;
    const u64* vbe2 = (const u64*)(sw) + 1015;
    const u64* vbe3 = (const u64*)(sw) + 1025;
    const u64* vbd1 = (const u64*)(sw) + 1030;
    const u64* vbd2 = (const u64*)(sw) + 1040;
    const u64* vbd3 = (const u64*)(sw) + 1055;

    // pack activations: lane-wise (node0, node1)
    u64 x[20];
    {
        const float* r0 = se + tid * EMB_PAD;
        const float* r1 = se + (tid + MLP_BLK) * EMB_PAD;
#pragma unroll
        for (int jx = 0; jx < 20; jx++) x[jx] = pk2(r0[jx], r1[jx]);
    }

    u64 h1v[15];
#pragma unroll
    for (int i = 0; i < 15; i++) {
        u64 a = vbe1[i];
#pragma unroll
        for (int jx = 0; jx < 20; jx++) a = fma2(wWe1[i * 20 + jx], x[jx], a);
        h1v[i] = relu2(a);
    }
    u64 h2v[10];
#pragma unroll
    for (int i = 0; i < 10; i++) {
        u64 a = vbe2[i];
#pragma unroll
        for (int jx = 0; jx < 15; jx++) a = fma2(wWe2[i * 15 + jx], h1v[jx], a);
        h2v[i] = relu2(a);
    }
    u64 ev[5];
#pragma unroll
    for (int i = 0; i < 5; i++) {
        u64 a = vbe3[i];
#pragma unroll
        for (int jx = 0; jx < 10; jx++) a = fma2(wWe3[i * 10 + jx], h2v[jx], a);
        ev[i] = a;                                    // encoded: no relu
    }
#pragma unroll
    for (int i = 0; i < 5; i++) {
        float e0, e1; up2(ev[i], e0, e1);
        if (n0 < N) enc_out[(size_t)n0 * 5 + i] = e0;
        if (n1 < N) enc_out[(size_t)n1 * 5 + i] = e1;
    }

    u64 d1v[10];
#pragma unroll
    for (int i = 0; i < 10; i++) {
        u64 a = vbd1[i];
#pragma unroll
        for (int jx = 0; jx < 5; jx++) a = fma2(wWd1[i * 5 + jx], ev[jx], a);
        d1v[i] = relu2(a);
    }
    u64 d2v[15];
#pragma unroll
    for (int i = 0; i < 15; i++) {
        u64 a = vbd2[i];
#pragma unroll
        for (int jx = 0; jx < 10; jx++) a = fma2(wWd2[i * 10 + jx], d1v[jx], a);
        d2v[i] = relu2(a);
    }
    // decoded -> own two rows of se (only this thread ever touches them)
#pragma unroll
    for (int i = 0; i < 20; i++) {
        u64 a = vbd3[i];
#pragma unroll
        for (int jx = 0; jx < 15; jx++) a = fma2(wWd3[i * 15 + jx], d2v[jx], a);
        float d0, d1; up2(a, d0, d1);
        se[tid * EMB_PAD + i]             = d0;
        se[(tid + MLP_BLK) * EMB_PAD + i] = d1;
    }
    __syncthreads();

    // coalesced float4 export of decoded tile
#pragma unroll
    for (int i = 0; i < 10; i++) {
        int  lf4 = tid + i * MLP_BLK;
        long f4  = f4base + lf4;
        if (f4 < f4total) {
            int rr = lf4 / 5, q = lf4 % 5;
            const float* s = se + rr * EMB_PAD + q * 4;
            reinterpret_cast<float4*>(dec_out)[f4] =
                make_float4(s[0], s[1], s[2], s[3]);
        }
    }
}

// ---------------------------------------------------------------------------
extern "C" void kernel_launch(void* const* d_in, const int* in_sizes, int n_in,
                              void* d_out, int out_size)
{
    const float* features = (const float*)d_in[0];
    const int*   adj      = (const int*)d_in[1];
    const float* We1 = (const float*)d_in[2];  const float* be1 = (const float*)d_in[3];
    const float* We2 = (const float*)d_in[4];  const float* be2 = (const float*)d_in[5];
    const float* We3 = (const float*)d_in[6];  const float* be3 = (const float*)d_in[7];
    const float* Wd1 = (const float*)d_in[8];  const float* bd1 = (const float*)d_in[9];
    const float* Wd2 = (const float*)d_in[10]; const float* bd2 = (const float*)d_in[11];
    const float* Wd3 = (const float*)d_in[12]; const float* bd3 = (const float*)d_in[13];

    int N = in_sizes[0] / NODELEN;

    float* out = (float*)d_out;
    float* enc_out = out;                     // [N,5]
    float* dec_out = out + (size_t)N * 5;     // [N,20]
    float* emb_out = out + (size_t)N * 25;    // [N,20]

    int pack_blocks = (N * PADH + 255) / 256;
    pack_features_kernel<<<pack_blocks, 256>>>(features, N);

    // one warp per 2 nodes, 8 warps/block -> 16 nodes/block
    int hop_blocks = (N + 15) / 16;
    hop1_kernel<<<hop_blocks, 256>>>(adj, N);
    hop2_emb_kernel<<<hop_blocks, 256>>>(features, adj, emb_out, N);

    int mlp_blocks = (N + MLP_TILE - 1) / MLP_TILE;
    mlp_kernel<<<mlp_blocks, MLP_BLK>>>(emb_out,
                                        We1, be1, We2, be2, We3, be3,
                                        Wd1, bd1, Wd2, bd2, Wd3, bd3,
                                        enc_out, dec_out, N);
}

// round 8
// speedup vs baseline: 1.0030x; 1.0030x over previous
#include <cuda_runtime.h>
#include <cuda_fp16.h>

#define NODELEN 10
#define DEG 32
#define MAXN 200000
#define PADH 16   // halves per row: 32B = one sector, sector-aligned

// Allocation-free scratch: fp16 gather tables, one sector per row.
__device__ __half g_featH[(size_t)MAXN * PADH];
__device__ __half g_h1H[(size_t)MAXN * PADH];

// ---------------------------------------------------------------------------
// Pack: features [N,10] fp32 -> g_featH [N,16] fp16 (zero padded).
// ---------------------------------------------------------------------------
__global__ __launch_bounds__(256) void pack_features_kernel(
    const float* __restrict__ features, int N)
{
    int idx = blockIdx.x * blockDim.x + threadIdx.x;
    if (idx >= N * PADH) return;
    int n = idx >> 4;
    int k = idx & 15;
    float v = (k < NODELEN) ? features[(size_t)n * NODELEN + k] : 0.f;
    g_featH[idx] = __float2half_rn(v);
}

// ---------------------------------------------------------------------------
// Hop kernels: one warp per TWO nodes (16 independent gather LDGs in flight).
// Each gathered row = 16 halves = 32B = ONE sector -> 1 L1tex wavefront/row.
// ---------------------------------------------------------------------------
__global__ __launch_bounds__(256) void hop1_kernel(
    const int* __restrict__ adj, int N)
{
    int w    = (blockIdx.x * blockDim.x + threadIdx.x) >> 5;
    int lane = threadIdx.x & 31;
    int n0 = 2 * w, n1 = 2 * w + 1;
    if (n0 >= N) return;
    bool has1 = (n1 < N);

    int nb0 = adj[(size_t)n0 * DEG + lane];
    int nb1 = has1 ? adj[(size_t)n1 * DEG + lane] : nb0;

    int r = lane >> 3, j = lane & 7;
    float2 a0 = make_float2(0.f, 0.f), a1 = make_float2(0.f, 0.f);
#pragma unroll
    for (int i = 0; i < 8; i++) {
        int m0 = __shfl_sync(0xffffffffu, nb0, 4 * i + r);
        int m1 = __shfl_sync(0xffffffffu, nb1, 4 * i + r);
        float2 v0 = __half22float2(*reinterpret_cast<const __half2*>(
            g_featH + (size_t)m0 * PADH + 2 * j));
        float2 v1 = __half22float2(*reinterpret_cast<const __half2*>(
            g_featH + (size_t)m1 * PADH + 2 * j));
        a0.x += v0.x; a0.y += v0.y;
        a1.x += v1.x; a1.y += v1.y;
    }
#pragma unroll
    for (int off = 8; off < 32; off <<= 1) {
        a0.x += __shfl_xor_sync(0xffffffffu, a0.x, off);
        a0.y += __shfl_xor_sync(0xffffffffu, a0.y, off);
        a1.x += __shfl_xor_sync(0xffffffffu, a1.x, off);
        a1.y += __shfl_xor_sync(0xffffffffu, a1.y, off);
    }

    if (lane < 16) {
        int   node = (lane >> 3) ? n1 : n0;
        float2 s   = (lane >> 3) ? a1 : a0;
        if (node < N) {
            float vx = s.x * (1.f / 32.f);
            float vy = s.y * (1.f / 32.f);
            if (j == 0) vx = 0.f;            // h1[:,0] = 0
            *reinterpret_cast<__half2*>(g_h1H + (size_t)node * PADH + 2 * j) =
                __floats2half2_rn(vx, vy);
        }
    }
}

__global__ __launch_bounds__(256) void hop2_emb_kernel(
    const float* __restrict__ features, const int* __restrict__ adj,
    float* __restrict__ emb, int N)
{
    int w    = (blockIdx.x * blockDim.x + threadIdx.x) >> 5;
    int lane = threadIdx.x & 31;
    int n0 = 2 * w, n1 = 2 * w + 1;
    if (n0 >= N) return;
    bool has1 = (n1 < N);

    int nb0 = adj[(size_t)n0 * DEG + lane];
    int nb1 = has1 ? adj[(size_t)n1 * DEG + lane] : nb0;

    int r = lane >> 3, j = lane & 7;
    float2 a0 = make_float2(0.f, 0.f), a1 = make_float2(0.f, 0.f);
#pragma unroll
    for (int i = 0; i < 8; i++) {
        int m0 = __shfl_sync(0xffffffffu, nb0, 4 * i + r);
        int m1 = __shfl_sync(0xffffffffu, nb1, 4 * i + r);
        float2 v0 = __half22float2(*reinterpret_cast<const __half2*>(
            g_h1H + (size_t)m0 * PADH + 2 * j));
        float2 v1 = __half22float2(*reinterpret_cast<const __half2*>(
            g_h1H + (size_t)m1 * PADH + 2 * j));
        a0.x += v0.x; a0.y += v0.y;
        a1.x += v1.x; a1.y += v1.y;
    }
#pragma unroll
    for (int off = 8; off < 32; off <<= 1) {
        a0.x += __shfl_xor_sync(0xffffffffu, a0.x, off);
        a0.y += __shfl_xor_sync(0xffffffffu, a0.y, off);
        a1.x += __shfl_xor_sync(0xffffffffu, a1.x, off);
        a1.y += __shfl_xor_sync(0xffffffffu, a1.y, off);
    }

    // agg part: cols 10..19 (pairs j=0..4), col 10 zeroed
    if (lane < 16 && j < 5) {
        int    node = (lane >> 3) ? n1 : n0;
        float2 s    = (lane >> 3) ? a1 : a0;
        if (node < N) {
            float2 v;
            v.x = s.x * (1.f / 32.f);
            v.y = s.y * (1.f / 32.f);
            if (j == 0) v.x = 0.f;           // emb[:,NODELEN] = 0
            *reinterpret_cast<float2*>(emb + (size_t)node * 20 + 10 + 2 * j) = v;
        }
    }
    // self features: cols 0..9, col 0 zeroed (exact fp32 from input)
    if (lane >= 12) {
        int d, node;
        if (lane < 22) { d = lane - 12; node = n0; }
        else           { d = lane - 22; node = n1; }
        if (node < N) {
            float f = (d == 0) ? 0.f : features[(size_t)node * NODELEN + d];
            emb[(size_t)node * 20 + d] = f;
        }
    }
}

// ---------------------------------------------------------------------------
// MLP autoencoder: ONE node per thread; two OUTPUT NEURONS packed per f32x2
// accumulator. Weights stored transposed-paired in smem:
//   w[j*P + p] = (W[2p][j], W[2p+1][j])   (consecutive p -> LDS.128 fusable)
// Input x_j broadcast to both halves once per j, reused across all p.
// Odd output widths padded to even with zero rows.
// ---------------------------------------------------------------------------
#define MLP_BLK 256
#define EMB_PAD 21   // odd stride -> conflict-free LDS

typedef unsigned long long u64;

__device__ __forceinline__ u64 pk2(float lo, float hi) {
    u64 r; asm("mov.b64 %0,{%1,%2};" : "=l"(r) : "f"(lo), "f"(hi)); return r;
}
__device__ __forceinline__ void up2(u64 v, float& lo, float& hi) {
    asm("mov.b64 {%0,%1},%2;" : "=f"(lo), "=f"(hi) : "l"(v));
}
__device__ __forceinline__ u64 fma2(u64 a, u64 b, u64 c) {
    u64 d; asm("fma.rn.f32x2 %0,%1,%2,%3;" : "=l"(d) : "l"(a), "l"(b), "l"(c));
    return d;
}

// One dense layer: out[2p],out[2p+1] = (relu?) ( sum_j W[2p..2p+1][j]*in[j] + b )
template<int I, int P, bool RELU>
__device__ __forceinline__ void layer2(const u64* __restrict__ w,
                                       const u64* __restrict__ b,
                                       const float* __restrict__ in,
                                       float* __restrict__ out)
{
    u64 acc[P];
#pragma unroll
    for (int p = 0; p < P; p++) acc[p] = b[p];
#pragma unroll
    for (int j = 0; j < I; j++) {
        float xv = in[j];
        u64 xj = pk2(xv, xv);
#pragma unroll
        for (int p = 0; p < P; p++)
            acc[p] = fma2(w[j * P + p], xj, acc[p]);
    }
#pragma unroll
    for (int p = 0; p < P; p++) {
        float lo, hi; up2(acc[p], lo, hi);
        if (RELU) { lo = fmaxf(lo, 0.f); hi = fmaxf(hi, 0.f); }
        out[2 * p]     = lo;
        out[2 * p + 1] = hi;
    }
}

// smem u64 offsets for the 6 layers (W then biases)
#define OFF_W1 0      // 20*8  = 160
#define OFF_W2 160    // 15*5  = 75
#define OFF_W3 235    // 10*3  = 30
#define OFF_W4 265    // 5*5   = 25
#define OFF_W5 290    // 10*8  = 80
#define OFF_W6 370    // 15*10 = 150
#define OFF_B1 520
#define OFF_B2 528
#define OFF_B3 533
#define OFF_B4 536
#define OFF_B5 541
#define OFF_B6 549
#define SW_U64 560

__global__ __launch_bounds__(MLP_BLK) void mlp_kernel(
    const float* __restrict__ emb,
    const float* __restrict__ We1, const float* __restrict__ be1,
    const float* __restrict__ We2, const float* __restrict__ be2,
    const float* __restrict__ We3, const float* __restrict__ be3,
    const float* __restrict__ Wd1, const float* __restrict__ bd1,
    const float* __restrict__ Wd2, const float* __restrict__ bd2,
    const float* __restrict__ Wd3, const float* __restrict__ bd3,
    float* __restrict__ enc_out, float* __restrict__ dec_out, int N)
{
    __shared__ __align__(16) u64 sw[SW_U64];
    __shared__ float se[MLP_BLK * EMB_PAD];

    const int tid = threadIdx.x;

    // Build transposed-paired weights + paired biases.
    {
        const float* Ws[6] = {We1, We2, We3, Wd1, Wd2, Wd3};
        const float* Bs[6] = {be1, be2, be3, bd1, bd2, bd3};
        const int Is[6]   = {20, 15, 10, 5, 10, 15};
        const int Os[6]   = {15, 10, 5, 10, 15, 20};
        const int Ps[6]   = {8, 5, 3, 5, 8, 10};
        const int oW[6]   = {OFF_W1, OFF_W2, OFF_W3, OFF_W4, OFF_W5, OFF_W6};
        const int oB[6]   = {OFF_B1, OFF_B2, OFF_B3, OFF_B4, OFF_B5, OFF_B6};
        for (int l = 0; l < 6; l++) {
            int I = Is[l], O = Os[l], P = Ps[l];
            const float* W = Ws[l];
            for (int idx = tid; idx < I * P; idx += MLP_BLK) {
                int j = idx / P, p = idx % P;
                int r0 = 2 * p, r1 = 2 * p + 1;
                float w0 = (r0 < O) ? W[r0 * I + j] : 0.f;
                float w1 = (r1 < O) ? W[r1 * I + j] : 0.f;
                reinterpret_cast<float2*>(sw)[oW[l] + idx] = make_float2(w0, w1);
            }
            const float* B = Bs[l];
            for (int p = tid; p < P; p += MLP_BLK) {
                int r0 = 2 * p, r1 = 2 * p + 1;
                float b0 = (r0 < O) ? B[r0] : 0.f;
                float b1 = (r1 < O) ? B[r1] : 0.f;
                reinterpret_cast<float2*>(sw)[oB[l] + p] = make_float2(b0, b1);
            }
        }
    }

    // Stage emb tile: coalesced float4 loads, OOB rows zeroed.
    const int  base    = blockIdx.x * MLP_BLK;
    const long f4base  = (long)base * 5;
    const long f4total = (long)N * 5;
#pragma unroll
    for (int i = 0; i < 5; i++) {
        int  lf4 = tid + i * MLP_BLK;                 // 0..1279
        long f4  = f4base + lf4;
        float4 t = (f4 < f4total) ? reinterpret_cast<const float4*>(emb)[f4]
                                  : make_float4(0.f, 0.f, 0.f, 0.f);
        int rr = lf4 / 5, q = lf4 % 5;
        float* d = se + rr * EMB_PAD + q * 4;
        d[0] = t.x; d[1] = t.y; d[2] = t.z; d[3] = t.w;
    }
    __syncthreads();

    const int n = base + tid;
    float* myrow = se + tid * EMB_PAD;

    float h1v[16], h2v[10], ev[6], d1v[10], d2v[16];

    layer2<20, 8, true >(sw + OFF_W1, sw + OFF_B1, myrow, h1v);
    layer2<15, 5, true >(sw + OFF_W2, sw + OFF_B2, h1v,   h2v);
    layer2<10, 3, false>(sw + OFF_W3, sw + OFF_B3, h2v,   ev);

    if (n < N) {
#pragma unroll
        for (int i = 0; i < 5; i++) enc_out[(size_t)n * 5 + i] = ev[i];
    }

    layer2< 5, 5, true >(sw + OFF_W4, sw + OFF_B4, ev,  d1v);
    layer2<10, 8, true >(sw + OFF_W5, sw + OFF_B5, d1v, d2v);
    // decoded: write straight into own se row (only this thread touches it)
    layer2<15, 10, false>(sw + OFF_W6, sw + OFF_B6, d2v, myrow);

    __syncthreads();

    // Coalesced float4 export of decoded tile.
#pragma unroll
    for (int i = 0; i < 5; i++) {
        int  lf4 = tid + i * MLP_BLK;
        long f4  = f4base + lf4;
        if (f4 < f4total) {
            int rr = lf4 / 5, q = lf4 % 5;
            const float* s = se + rr * EMB_PAD + q * 4;
            reinterpret_cast<float4*>(dec_out)[f4] =
                make_float4(s[0], s[1], s[2], s[3]);
        }
    }
}

// ---------------------------------------------------------------------------
extern "C" void kernel_launch(void* const* d_in, const int* in_sizes, int n_in,
                              void* d_out, int out_size)
{
    const float* features = (const float*)d_in[0];
    const int*   adj      = (const int*)d_in[1];
    const float* We1 = (const float*)d_in[2];  const float* be1 = (const float*)d_in[3];
    const float* We2 = (const float*)d_in[4];  const float* be2 = (const float*)d_in[5];
    const float* We3 = (const float*)d_in[6];  const float* be3 = (const float*)d_in[7];
    const float* Wd1 = (const float*)d_in[8];  const float* bd1 = (const float*)d_in[9];
    const float* Wd2 = (const float*)d_in[10]; const float* bd2 = (const float*)d_in[11];
    const float* Wd3 = (const float*)d_in[12]; const float* bd3 = (const float*)d_in[13];

    int N = in_sizes[0] / NODELEN;

    float* out = (float*)d_out;
    float* enc_out = out;                     // [N,5]
    float* dec_out = out + (size_t)N * 5;     // [N,20]
    float* emb_out = out + (size_t)N * 25;    // [N,20]

    int pack_blocks = (N * PADH + 255) / 256;
    pack_features_kernel<<<pack_blocks, 256>>>(features, N);

    // one warp per 2 nodes, 8 warps/block -> 16 nodes/block
    int hop_blocks = (N + 15) / 16;
    hop1_kernel<<<hop_blocks, 256>>>(adj, N);
    hop2_emb_kernel<<<hop_blocks, 256>>>(features, adj, emb_out, N);

    int mlp_blocks = (N + MLP_BLK - 1) / MLP_BLK;
    mlp_kernel<<<mlp_blocks, MLP_BLK>>>(emb_out,
                                        We1, be1, We2, be2, We3, be3,
                                        Wd1, bd1, Wd2, bd2, Wd3, bd3,
                                        enc_out, dec_out, N);
}